// round 15
// baseline (speedup 1.0000x reference)
#include <cuda_runtime.h>
#include <cuda_bf16.h>

// Problem constants (fixed shapes from setup_inputs)
#define BB      4
#define NPTS    8192
#define SS      2048
#define CC      64
#define NSAMPLE 32
#define R2      0.04f     // 0.2^2
#define OUTCH   (3 + CC)  // 67

#define WPB     2         // warps per block (qg)
#define TSTRIDE 132       // transpose smem row stride (floats) — mult of 4
#define NPAIR   (NPTS / 2)

// Scratch: transposed features [B,N,C] (8MB); paired point planes (512KB):
//   planeA[pair] = (x0, x1, y0, y1), planeB[pair] = (z0, z1, p2_0, p2_1)
__device__ float  g_featT[(size_t)BB * NPTS * CC];
__device__ float4 g_pairA[(size_t)BB * NPAIR];
__device__ float4 g_pairB[(size_t)BB * NPAIR];

// ---- packed f32x2 helpers (per-lane IEEE .rn — bit-identical to scalar) ----
__device__ __forceinline__ unsigned long long f2mul(unsigned long long a,
                                                    unsigned long long b) {
    unsigned long long o;
    asm("mul.rn.f32x2 %0, %1, %2;" : "=l"(o) : "l"(a), "l"(b));
    return o;
}
__device__ __forceinline__ unsigned long long f2add(unsigned long long a,
                                                    unsigned long long b) {
    unsigned long long o;
    asm("add.rn.f32x2 %0, %1, %2;" : "=l"(o) : "l"(a), "l"(b));
    return o;
}
__device__ __forceinline__ unsigned long long f2pack(float lo, float hi) {
    unsigned long long o;
    asm("mov.b64 %0, {%1, %2};" : "=l"(o) : "f"(lo), "f"(hi));
    return o;
}
__device__ __forceinline__ void f2unpack(float& lo, float& hi,
                                         unsigned long long v) {
    asm("mov.b64 {%0, %1}, %2;" : "=f"(lo), "=f"(hi) : "l"(v));
}

// ---------------------------------------------------------------------------
// Kernel 1: transpose features [B,C,N] -> [B,N,C] (round-13, validated).
// Last y-slice packs point PAIRS: planeA=(x0,x1,y0,y1), planeB=(z0,z1,p2s),
// p2 in EXACT reference rounding.
// ---------------------------------------------------------------------------
__global__ __launch_bounds__(256) void transpose_kernel(
    const float* __restrict__ feat,
    const float* __restrict__ xyz)
{
    const int b = blockIdx.z;

    if (blockIdx.y == CC / 32) {
        // pair pack: 64 pairs (128 points) per block, threads 0..63
        const int t = threadIdx.y * 8 + threadIdx.x;
        if (t < 64) {
            const int p  = blockIdx.x * 64 + t;       // pair id
            const int n0 = 2 * p;
            const float* s0 = xyz + ((size_t)b * NPTS + n0) * 3;
            const float x0 = __ldg(s0 + 0), y0 = __ldg(s0 + 1), z0 = __ldg(s0 + 2);
            const float x1 = __ldg(s0 + 3), y1 = __ldg(s0 + 4), z1 = __ldg(s0 + 5);
            const float p20 = __fadd_rn(__fadd_rn(__fmul_rn(x0, x0),
                                                  __fmul_rn(y0, y0)),
                                        __fmul_rn(z0, z0));
            const float p21 = __fadd_rn(__fadd_rn(__fmul_rn(x1, x1),
                                                  __fmul_rn(y1, y1)),
                                        __fmul_rn(z1, z1));
            g_pairA[(size_t)b * NPAIR + p] = make_float4(x0, x1, y0, y1);
            g_pairB[(size_t)b * NPAIR + p] = make_float4(z0, z1, p20, p21);
        }
        return;
    }

    __shared__ float tile[32 * TSTRIDE];

    const int n0 = blockIdx.x * 128;
    const int c0 = blockIdx.y * 32;
    const int tx = threadIdx.x;            // 0..7
    const int ty = threadIdx.y;            // 0..31

    const float* fb = feat + ((size_t)b * CC + c0 + ty) * NPTS + n0;
#pragma unroll
    for (int i = 0; i < 4; i++) {
        const float4 v = __ldg((const float4*)(fb + i * 32) + tx);
        *(float4*)&tile[ty * TSTRIDE + i * 32 + 4 * tx] = v;
    }
    __syncthreads();

    float* fT = g_featT + (size_t)b * NPTS * CC;
#pragma unroll
    for (int i = 0; i < 4; i++) {
        const int n = i * 32 + ty;
        float4 o;
        o.x = tile[(4 * tx + 0) * TSTRIDE + n];
        o.y = tile[(4 * tx + 1) * TSTRIDE + n];
        o.z = tile[(4 * tx + 2) * TSTRIDE + n];
        o.w = tile[(4 * tx + 3) * TSTRIDE + n];
        *(float4*)(fT + (size_t)(n0 + n) * CC + c0 + 4 * tx) = o;
    }
}

// ---------------------------------------------------------------------------
// Kernel 2: fused ball query + group. One warp per query, 2 warps/block.
// Scan: packed f32x2 distance tests (2 points/lane/step, bit-identical
// rounding), ping-pong prefetch, skip-empty chunks.
// Gather: round-13 wavefront-optimal pattern (validated).
// ---------------------------------------------------------------------------
__global__ __launch_bounds__(64) void qg_kernel(
    const float* __restrict__ new_xyz,  // [B, S, 3]
    float* __restrict__ out)            // [B, 67, S, 32]
{
    __shared__ int   sidx[WPB][NSAMPLE];
    __shared__ float tile[WPB][NSAMPLE * 33];

    const int warp = threadIdx.x >> 5;
    const int lane = threadIdx.x & 31;
    const int w    = blockIdx.x * WPB + warp;  // query id in [0, B*S)
    const int b    = w / SS;
    const int s    = w % SS;

    const float* qptr = new_xyz + ((size_t)b * SS + s) * 3;
    const float qx = qptr[0], qy = qptr[1], qz = qptr[2];
    // Reference arithmetic EXACTLY (plain rn ops, no contraction):
    const float q2 = __fadd_rn(__fadd_rn(__fmul_rn(qx, qx), __fmul_rn(qy, qy)),
                               __fmul_rn(qz, qz));

    // Broadcast packed query constants
    const unsigned long long qx2 = f2pack(qx, qx);
    const unsigned long long qy2 = f2pack(qy, qy);
    const unsigned long long qz2 = f2pack(qz, qz);
    const unsigned long long q22 = f2pack(q2, q2);
    const unsigned long long m22 = f2pack(-2.0f, -2.0f);

    const ulonglong2* pA =
        reinterpret_cast<const ulonglong2*>(g_pairA) + (size_t)b * NPAIR;
    const ulonglong2* pB =
        reinterpret_cast<const ulonglong2*>(g_pairB) + (size_t)b * NPAIR;

    const unsigned lmask  = (1u << lane) - 1u;        // lanes < me
    const unsigned lmaskE = lmask | (1u << lane);     // lanes <= me

    int cnt = 0;

    // Evaluate one 64-point pair-round: a=(x01,y01), c=(z01,w01); pair id pi.
    auto pround = [&](ulonglong2 a, ulonglong2 c, int pi) {
        const unsigned long long qpd =
            f2add(f2add(f2mul(qx2, a.x), f2mul(qy2, a.y)), f2mul(qz2, c.x));
        const unsigned long long d2 =
            f2add(f2add(q22, c.y), f2mul(m22, qpd));
        float dlo, dhi;
        f2unpack(dlo, dhi, d2);
        const bool ie = dlo < R2;                 // even point 2*pi
        const bool io = dhi < R2;                 // odd  point 2*pi+1
        const unsigned me = __ballot_sync(0xffffffffu, ie);
        const unsigned mo = __ballot_sync(0xffffffffu, io);
        if ((me | mo) != 0u) {
            if (ie) {
                const int pos = cnt + __popc(me & lmask) + __popc(mo & lmask);
                if (pos < NSAMPLE) sidx[warp][pos] = 2 * pi;
            }
            if (io) {
                const int pos = cnt + __popc(me & lmaskE) + __popc(mo & lmask);
                if (pos < NSAMPLE) sidx[warp][pos] = 2 * pi + 1;
            }
            cnt += __popc(me) + __popc(mo);
        }
    };

    // Ping-pong scan, 128 points (2 pair-rounds) per chunk.
    {
        ulonglong2 A0, C0, A1, C1, B0, D0, B1, D1;
        A0 = __ldg(pA + lane);        C0 = __ldg(pB + lane);
        A1 = __ldg(pA + 32 + lane);   C1 = __ldg(pB + 32 + lane);

        int pbase = 0;                      // pair index of chunk start
        for (;;) {
            if (pbase + 64 < NPAIR) {
                B0 = __ldg(pA + pbase + 64 + lane);
                D0 = __ldg(pB + pbase + 64 + lane);
                B1 = __ldg(pA + pbase + 96 + lane);
                D1 = __ldg(pB + pbase + 96 + lane);
            }
            pround(A0, C0, pbase + lane);
            pround(A1, C1, pbase + 32 + lane);
            pbase += 64;
            if (cnt >= NSAMPLE || pbase >= NPAIR) break;

            if (pbase + 64 < NPAIR) {
                A0 = __ldg(pA + pbase + 64 + lane);
                C0 = __ldg(pB + pbase + 64 + lane);
                A1 = __ldg(pA + pbase + 96 + lane);
                C1 = __ldg(pB + pbase + 96 + lane);
            }
            pround(B0, D0, pbase + lane);
            pround(B1, D1, pbase + 32 + lane);
            pbase += 64;
            if (cnt >= NSAMPLE || pbase >= NPAIR) break;
        }
    }

    // Empty-ball fallback: slot 0 = point 0 (matches reference idx=0)
    if (cnt == 0 && lane == 0) sidx[warp][0] = 0;
    __syncwarp();

    const int total = (cnt == 0) ? 1 : ((cnt < NSAMPLE) ? cnt : NSAMPLE);
    const int slot  = (lane < total) ? lane : 0;     // pad with first
    const int myidx = sidx[warp][slot];

    // --- grouped_xyz = xyz[idx] - new_xyz (re-load identical bits) ---------
    {
        const float4 a = __ldg((const float4*)g_pairA + (size_t)b * NPAIR + (myidx >> 1));
        const float4 c = __ldg((const float4*)g_pairB + (size_t)b * NPAIR + (myidx >> 1));
        const bool odd = (myidx & 1) != 0;
        const float gx = odd ? a.y : a.x;
        const float gy = odd ? a.w : a.z;
        const float gz = odd ? c.y : c.x;
        const size_t cs    = (size_t)SS * NSAMPLE;
        const size_t obase = (((size_t)b * OUTCH) * SS + s) * NSAMPLE + lane;
        out[obase + 0 * cs] = gx - qx;
        out[obase + 1 * cs] = gy - qy;
        out[obase + 2 * cs] = gz - qz;
    }

    // --- grouped_features: wavefront-optimal cooperative gather -------------
    const float* fT = g_featT + (size_t)b * NPTS * CC;
    float*       tw = tile[warp];

    const int csub = lane >> 3;       // store: channel sub-id (0..3)
    const int k4   = (lane & 7) * 4;  // store: first of 4 samples

#pragma unroll
    for (int h = 0; h < 2; h++) {     // two 32-channel halves
        // 32 coalesced 128B half-row loads (1 wavefront each), MLP=8
#pragma unroll
        for (int m0 = 0; m0 < NSAMPLE; m0 += 8) {
            float v[8];
#pragma unroll
            for (int mm = 0; mm < 8; mm++) {
                const int im = __shfl_sync(0xffffffffu, myidx, m0 + mm);
                v[mm] = __ldg(fT + (size_t)im * CC + h * 32 + lane);
            }
#pragma unroll
            for (int mm = 0; mm < 8; mm++)
                tw[(m0 + mm) * 33 + lane] = v[mm];
        }
        __syncwarp();
        // 8 STG.128: each instr covers 4 channels x 8 sample-quads.
        // LDS banks: (k4+j)*33 + c == k4+j+c (mod 32) -> conflict-free
#pragma unroll
        for (int cc = 0; cc < 8; cc++) {
            const int c = cc * 4 + csub;          // channel within half
            float4 o;
            o.x = tw[(k4 + 0) * 33 + c];
            o.y = tw[(k4 + 1) * 33 + c];
            o.z = tw[(k4 + 2) * 33 + c];
            o.w = tw[(k4 + 3) * 33 + c];
            float* dst = out + (((size_t)b * OUTCH + 3 + h * 32 + c) * SS + s)
                             * NSAMPLE + k4;
            *(float4*)dst = o;
        }
        __syncwarp();
    }
}

extern "C" void kernel_launch(void* const* d_in, const int* in_sizes, int n_in,
                              void* d_out, int out_size) {
    const float* xyz      = (const float*)d_in[0];   // [4, 8192, 3]
    const float* new_xyz  = (const float*)d_in[1];   // [4, 2048, 3]
    const float* features = (const float*)d_in[2];   // [4, 64, 8192]
    float* out = (float*)d_out;                      // [4, 67, 2048, 32]

    dim3 tb(8, 32);
    dim3 tg(NPTS / 128, CC / 32 + 1, BB);            // (64, 3, 4)
    transpose_kernel<<<tg, tb>>>(features, xyz);

    qg_kernel<<<(BB * SS) / WPB, 32 * WPB>>>(new_xyz, out);  // 4096 x 64
}